// round 3
// baseline (speedup 1.0000x reference)
#include <cuda_runtime.h>
#include <cstdint>
#include <cstddef>

// Problem constants
#define HH 2048
#define BB 256
#define TT 200
#define VV 512
#define LL 2

// ---------------------------------------------------------------------------
// Scratch (static __device__ — no allocations allowed)
// ---------------------------------------------------------------------------
__device__ __align__(128) float g_Eprime[VV * HH];    // emb@W_ih0^T + b_ih0 + b_hh0 (fp32)
__device__ __align__(128) float g_h0[2][BB * HH];     // layer-0 hidden, ping-pong (fp32)
__device__ __align__(128) float g_h1[2][BB * HH];     // layer-1 hidden, ping-pong (fp32)
__device__ __align__(128) float g_outs[(size_t)TT * BB * HH];  // layer-1 outputs (fp32)

// ---------------------------------------------------------------------------
// Helpers
// ---------------------------------------------------------------------------

// 2-term tf32 split: x = hi + lo + O(2^-22 x). hi = tf32_rna(x) is within
// half-ulp(10-bit) of x so (x - hi) is exact in fp32; lo = tf32_rna(x - hi).
__device__ __forceinline__ void tf32_split(float x, uint32_t& hi, uint32_t& lo) {
    uint32_t h;
    asm("cvt.rna.tf32.f32 %0, %1;\n" : "=r"(h) : "f"(x));
    float r = x - __uint_as_float(h);
    uint32_t l;
    asm("cvt.rna.tf32.f32 %0, %1;\n" : "=r"(l) : "f"(r));
    hi = h; lo = l;
}

// tanh immune to --use_fast_math's tanh.approx (too inaccurate).
__device__ __forceinline__ float my_tanh(float x) {
    float e = __expf(2.0f * x);
    return 1.0f - 2.0f / (e + 1.0f);
}

__device__ __forceinline__ void cp16(void* dst, const void* src) {
    uint32_t d = (uint32_t)__cvta_generic_to_shared(dst);
    asm volatile("cp.async.cg.shared.global [%0], [%1], 16;\n" :: "r"(d), "l"(src));
}

__device__ __forceinline__ void mma8(float* c, const uint32_t* a, const uint32_t* b) {
    asm volatile(
        "mma.sync.aligned.m16n8k8.row.col.f32.tf32.tf32.f32 "
        "{%0,%1,%2,%3}, {%4,%5,%6,%7}, {%8,%9}, {%0,%1,%2,%3};\n"
        : "+f"(c[0]), "+f"(c[1]), "+f"(c[2]), "+f"(c[3])
        : "r"(a[0]), "r"(a[1]), "r"(a[2]), "r"(a[3]),
          "r"(b[0]), "r"(b[1]));
}

// ---------------------------------------------------------------------------
// Prep: copy initial hidden state (fp32, unrounded)
// ---------------------------------------------------------------------------
__global__ void prep_kernel(const float* __restrict__ h0) {
    int idx = blockIdx.x * blockDim.x + threadIdx.x;
    int stride = gridDim.x * blockDim.x;
    for (int i = idx; i < BB * HH; i += stride) {
        g_h0[0][i] = h0[i];
        g_h1[0][i] = h0[BB * HH + i];
    }
}

// ---------------------------------------------------------------------------
// Generic fused GEMM: C[M,N] = A[M,K] @ W[N,K]^T (+ second A1@W1^T) + epilogue
// BM=BN=64, BK=32, 256 threads (8 warps), 3xTF32 mma (fp32-grade accuracy),
// cp.async 2-stage. All matrices have row stride HH (=2048).
// ---------------------------------------------------------------------------
#define MODE_EPRIME 0  // E'' = emb @ Wih0^T + b_ih0 + b_hh0        (M=512)
#define MODE_STEP0  1  // h0' = tanh(h0 @ Whh0^T + E''[tok[b,t]])   (M=256)
#define MODE_STEP1  2  // h1' = tanh(h0'@Wih1^T + h1@Whh1^T + b1)   (M=256, K=4096)
#define MODE_LOGITS 3  // logits = outs @ fcw^T + fc_b              (M=51200, N=512)

template <int MODE>
__global__ __launch_bounds__(256) void gemm_kernel(
    const int* __restrict__ tokens,
    const float* __restrict__ emb,
    const float* __restrict__ Wih,
    const float* __restrict__ Whh,
    const float* __restrict__ b_ih,
    const float* __restrict__ b_hh,
    const float* __restrict__ fcw,
    const float* __restrict__ fc_b,
    float* __restrict__ d_out,
    int t)
{
    __shared__ __align__(16) float As[2][64][36];
    __shared__ __align__(16) float Bs[2][64][36];

    const float *A0, *B0, *A1 = nullptr, *B1 = nullptr;
    int KT;
    const int p = t & 1;
    if (MODE == MODE_EPRIME)      { A0 = emb;          B0 = Wih;            KT = 64; }
    else if (MODE == MODE_STEP0)  { A0 = g_h0[p];      B0 = Whh;            KT = 64; }
    else if (MODE == MODE_STEP1)  { A0 = g_h0[p ^ 1];  B0 = Wih + HH * HH;
                                    A1 = g_h1[p];      B1 = Whh + HH * HH;  KT = 128; }
    else                          { A0 = g_outs;       B0 = fcw;            KT = 64; }

    const int m0 = blockIdx.x * 64;
    const int n0 = blockIdx.y * 64;
    const int tid = threadIdx.x;
    const int lane = tid & 31;
    const int warp = tid >> 5;
    const int wm = warp & 1;   // 2 warps over M (32 rows each)
    const int wn = warp >> 1;  // 4 warps over N (16 cols each)

    float acc[2][2][4];
#pragma unroll
    for (int i = 0; i < 2; i++)
#pragma unroll
        for (int j = 0; j < 2; j++)
#pragma unroll
            for (int k = 0; k < 4; k++) acc[i][j][k] = 0.0f;

    auto load_tile = [&](int kt, int s) {
        const float* sA = A0;
        const float* sB = B0;
        int kk = kt * 32;
        if (MODE == MODE_STEP1 && kt >= 64) { sA = A1; sB = B1; kk = (kt - 64) * 32; }
#pragma unroll
        for (int j = 0; j < 2; j++) {
            int chunk = tid + j * 256;
            int row = chunk >> 3;
            int c4 = (chunk & 7) * 4;
            cp16(&As[s][row][c4], sA + (size_t)(m0 + row) * HH + kk + c4);
            cp16(&Bs[s][row][c4], sB + (size_t)(n0 + row) * HH + kk + c4);
        }
        asm volatile("cp.async.commit_group;\n" ::: "memory");
    };

    load_tile(0, 0);

    for (int kt = 0; kt < KT; kt++) {
        const int s = kt & 1;
        if (kt + 1 < KT) {
            load_tile(kt + 1, s ^ 1);
            asm volatile("cp.async.wait_group 1;\n" ::: "memory");
        } else {
            asm volatile("cp.async.wait_group 0;\n" ::: "memory");
        }
        __syncthreads();

#pragma unroll
        for (int ks = 0; ks < 4; ks++) {
            const int kr = ks * 8 + (lane & 3);
            uint32_t ah[2][4], al[2][4], bh[2][2], bl[2][2];
            const int ar = wm * 32 + (lane >> 2);
#pragma unroll
            for (int mt = 0; mt < 2; mt++) {
                tf32_split(As[s][ar + mt * 16][kr],          ah[mt][0], al[mt][0]);
                tf32_split(As[s][ar + mt * 16 + 8][kr],      ah[mt][1], al[mt][1]);
                tf32_split(As[s][ar + mt * 16][kr + 4],      ah[mt][2], al[mt][2]);
                tf32_split(As[s][ar + mt * 16 + 8][kr + 4],  ah[mt][3], al[mt][3]);
            }
            const int bc = wn * 16 + (lane >> 2);
#pragma unroll
            for (int nt = 0; nt < 2; nt++) {
                tf32_split(Bs[s][bc + nt * 8][kr],      bh[nt][0], bl[nt][0]);
                tf32_split(Bs[s][bc + nt * 8][kr + 4],  bh[nt][1], bl[nt][1]);
            }
#pragma unroll
            for (int mt = 0; mt < 2; mt++)
#pragma unroll
                for (int nt = 0; nt < 2; nt++) {
                    mma8(acc[mt][nt], al[mt], bh[nt]);  // lo*hi correction
                    mma8(acc[mt][nt], ah[mt], bl[nt]);  // hi*lo correction
                    mma8(acc[mt][nt], ah[mt], bh[nt]);  // main term
                }
        }
        __syncthreads();
    }

    // Epilogue
#pragma unroll
    for (int mt = 0; mt < 2; mt++) {
#pragma unroll
        for (int hi = 0; hi < 2; hi++) {  // hi=0 -> c0/c1 rows, hi=1 -> +8 rows
            const int r = m0 + wm * 32 + mt * 16 + (lane >> 2) + hi * 8;
            int tokrow = 0;
            if (MODE == MODE_STEP0) tokrow = tokens[r * TT + t];
#pragma unroll
            for (int nt = 0; nt < 2; nt++) {
#pragma unroll
                for (int lo = 0; lo < 2; lo++) {
                    const int c = n0 + wn * 16 + nt * 8 + (lane & 3) * 2 + lo;
                    float v = acc[mt][nt][hi * 2 + lo];
                    if (MODE == MODE_EPRIME) {
                        v += b_ih[c] + b_hh[c];
                        g_Eprime[(size_t)r * HH + c] = v;
                    } else if (MODE == MODE_STEP0) {
                        v += g_Eprime[(size_t)tokrow * HH + c];
                        v = my_tanh(v);
                        g_h0[p ^ 1][(size_t)r * HH + c] = v;
                    } else if (MODE == MODE_STEP1) {
                        v += b_ih[HH + c] + b_hh[HH + c];
                        v = my_tanh(v);
                        g_h1[p ^ 1][(size_t)r * HH + c] = v;
                        g_outs[(size_t)t * BB * HH + (size_t)r * HH + c] = v;
                    } else {  // MODE_LOGITS
                        v += fc_b[c];
                        d_out[(size_t)r * VV + c] = v;
                    }
                }
            }
        }
    }
}

// ---------------------------------------------------------------------------
// h_final: [L,B,H] after t = T-1 (last step wrote parity 0)
// ---------------------------------------------------------------------------
__global__ void final_copy_kernel(float* __restrict__ d_out) {
    int i = blockIdx.x * blockDim.x + threadIdx.x;
    if (i < BB * HH) {
        d_out[(size_t)TT * BB * VV + i] = g_h0[0][i];
        d_out[(size_t)TT * BB * VV + BB * HH + i] = g_h1[0][i];
    }
}

// ---------------------------------------------------------------------------
// Launch
// ---------------------------------------------------------------------------
extern "C" void kernel_launch(void* const* d_in, const int* in_sizes, int n_in,
                              void* d_out, int out_size) {
    const int*   tokens = (const int*)d_in[0];
    const float* h0     = (const float*)d_in[1];
    const float* emb    = (const float*)d_in[2];
    const float* Wih    = (const float*)d_in[3];
    const float* Whh    = (const float*)d_in[4];
    const float* bih    = (const float*)d_in[5];
    const float* bhh    = (const float*)d_in[6];
    const float* fcw    = (const float*)d_in[7];
    const float* fcb    = (const float*)d_in[8];
    float* out = (float*)d_out;

    // 1) Initial hidden state
    prep_kernel<<<256, 256>>>(h0);

    // 2) E'' = emb @ W_ih0^T + b_ih0 + b_hh0 (turns layer-0 input GEMM into a gather)
    gemm_kernel<MODE_EPRIME><<<dim3(VV / 64, HH / 64), 256>>>(
        tokens, emb, Wih, Whh, bih, bhh, fcw, fcb, out, 0);

    // 3) Recurrence: 200 steps, 2 dependent GEMMs each
    for (int t = 0; t < TT; t++) {
        gemm_kernel<MODE_STEP0><<<dim3(BB / 64, HH / 64), 256>>>(
            tokens, emb, Wih, Whh, bih, bhh, fcw, fcb, out, t);
        gemm_kernel<MODE_STEP1><<<dim3(BB / 64, HH / 64), 256>>>(
            tokens, emb, Wih, Whh, bih, bhh, fcw, fcb, out, t);
    }

    // 4) Logits: [T*B, H] @ [V, H]^T + fc_b
    gemm_kernel<MODE_LOGITS><<<dim3((TT * BB) / 64, VV / 64), 256>>>(
        tokens, emb, Wih, Whh, bih, bhh, fcw, fcb, out, 0);

    // 5) h_final, if the output buffer has room for it after the logits
    if (out_size >= TT * BB * VV + LL * BB * HH)
        final_copy_kernel<<<(BB * HH + 255) / 256, 256>>>(out);
}

// round 4
// speedup vs baseline: 1.8904x; 1.8904x over previous
#include <cuda_runtime.h>
#include <cuda_fp16.h>
#include <cstdint>
#include <cstddef>

// Problem constants
#define HH 2048
#define BB 256
#define TT 200
#define VV 512
#define LL 2

#define LO_SCALE 4096.0f
#define LO_INV   (1.0f / 4096.0f)

// ---------------------------------------------------------------------------
// Scratch (static __device__ — no allocations allowed)
// All GEMM operands stored as fp16 (hi, lo*4096) pairs in separate arrays.
// ---------------------------------------------------------------------------
__device__ __align__(128) __half g_Wih0h[HH * HH];
__device__ __align__(128) __half g_Wih0l[HH * HH];
__device__ __align__(128) __half g_Whh0h[HH * HH];
__device__ __align__(128) __half g_Whh0l[HH * HH];
__device__ __align__(128) __half g_Wih1h[HH * HH];
__device__ __align__(128) __half g_Wih1l[HH * HH];
__device__ __align__(128) __half g_Whh1h[HH * HH];
__device__ __align__(128) __half g_Whh1l[HH * HH];
__device__ __align__(128) __half g_embh[VV * HH];
__device__ __align__(128) __half g_embl[VV * HH];
__device__ __align__(128) __half g_fcwh[VV * HH];
__device__ __align__(128) __half g_fcwl[VV * HH];
__device__ __align__(128) float  g_Eprime[VV * HH];       // epilogue-only, fp32
__device__ __align__(128) __half g_h0h[2][BB * HH];
__device__ __align__(128) __half g_h0l[2][BB * HH];
__device__ __align__(128) __half g_h1h[2][BB * HH];
__device__ __align__(128) __half g_h1l[2][BB * HH];
__device__ __align__(128) __half g_outsh[(size_t)TT * BB * HH];
__device__ __align__(128) __half g_outsl[(size_t)TT * BB * HH];

// ---------------------------------------------------------------------------
// Helpers
// ---------------------------------------------------------------------------

// fp16 split with scaled lo: x ≈ hi + lo/4096, residual ~2^-24 * |x|.
__device__ __forceinline__ void f16_split(float x, __half& hi, __half& lo) {
    __half h = __float2half_rn(x);
    float r = x - __half2float(h);             // exact in fp32
    hi = h;
    lo = __float2half_rn(r * LO_SCALE);        // scaled -> normal fp16 range
}

// tanh immune to --use_fast_math's tanh.approx (too inaccurate).
__device__ __forceinline__ float my_tanh(float x) {
    float e = __expf(2.0f * x);
    return 1.0f - 2.0f / (e + 1.0f);
}

__device__ __forceinline__ void cp16(uint32_t smem_addr, const void* src) {
    asm volatile("cp.async.cg.shared.global [%0], [%1], 16;\n"
                 :: "r"(smem_addr), "l"(src));
}

__device__ __forceinline__ void ldsm4(uint32_t* r, uint32_t addr) {
    asm volatile("ldmatrix.sync.aligned.m8n8.x4.shared.b16 {%0,%1,%2,%3}, [%4];\n"
                 : "=r"(r[0]), "=r"(r[1]), "=r"(r[2]), "=r"(r[3])
                 : "r"(addr));
}

__device__ __forceinline__ void mma16(float* c, const uint32_t* a, const uint32_t* b) {
    asm volatile(
        "mma.sync.aligned.m16n8k16.row.col.f32.f16.f16.f32 "
        "{%0,%1,%2,%3}, {%4,%5,%6,%7}, {%8,%9}, {%0,%1,%2,%3};\n"
        : "+f"(c[0]), "+f"(c[1]), "+f"(c[2]), "+f"(c[3])
        : "r"(a[0]), "r"(a[1]), "r"(a[2]), "r"(a[3]),
          "r"(b[0]), "r"(b[1]));
}

// ---------------------------------------------------------------------------
// Prep: split all weights + initial hidden state into fp16 hi/lo
// ---------------------------------------------------------------------------
__global__ void prep_kernel(const float* __restrict__ h0,
                            const float* __restrict__ emb,
                            const float* __restrict__ Wih,
                            const float* __restrict__ Whh,
                            const float* __restrict__ fcw) {
    int idx = blockIdx.x * blockDim.x + threadIdx.x;
    int stride = gridDim.x * blockDim.x;
    for (int i = idx; i < HH * HH; i += stride) {
        f16_split(Wih[i],           g_Wih0h[i], g_Wih0l[i]);
        f16_split(Wih[HH * HH + i], g_Wih1h[i], g_Wih1l[i]);
        f16_split(Whh[i],           g_Whh0h[i], g_Whh0l[i]);
        f16_split(Whh[HH * HH + i], g_Whh1h[i], g_Whh1l[i]);
    }
    for (int i = idx; i < VV * HH; i += stride) {
        f16_split(emb[i], g_embh[i], g_embl[i]);
        f16_split(fcw[i], g_fcwh[i], g_fcwl[i]);
    }
    for (int i = idx; i < BB * HH; i += stride) {
        f16_split(h0[i],           g_h0h[0][i], g_h0l[0][i]);
        f16_split(h0[BB * HH + i], g_h1h[0][i], g_h1l[0][i]);
    }
}

// ---------------------------------------------------------------------------
// Fused GEMM: C[M,N] = A @ W^T (+ second A1@W1^T) + epilogue, 2xFP16 split.
// BM=BN=64, BK=32, 256 threads (8 warps: 2 over M x 4 over N), double-buffered
// cp.async, ldmatrix fragment loads. Row stride HH everywhere.
// ---------------------------------------------------------------------------
#define MODE_EPRIME 0
#define MODE_STEP0  1
#define MODE_STEP1  2
#define MODE_LOGITS 3

#define ROWB 80      // bytes per smem row (40 halves)
#define STAGEB 5120  // bytes per stage (64 rows * 80B)

template <int MODE>
__global__ __launch_bounds__(256) void gemm_kernel(
    const int* __restrict__ tokens,
    const float* __restrict__ b_ih,
    const float* __restrict__ b_hh,
    const float* __restrict__ fc_b,
    float* __restrict__ d_out,
    int t)
{
    __shared__ __align__(16) __half Ash[2][64][40];
    __shared__ __align__(16) __half Asl[2][64][40];
    __shared__ __align__(16) __half Bsh[2][64][40];
    __shared__ __align__(16) __half Bsl[2][64][40];

    const __half *A0h, *A0l, *B0h, *B0l;
    const __half *A1h = nullptr, *A1l = nullptr, *B1h = nullptr, *B1l = nullptr;
    int KT;
    const int p = t & 1;
    if (MODE == MODE_EPRIME) {
        A0h = g_embh; A0l = g_embl; B0h = g_Wih0h; B0l = g_Wih0l; KT = 64;
    } else if (MODE == MODE_STEP0) {
        A0h = g_h0h[p]; A0l = g_h0l[p]; B0h = g_Whh0h; B0l = g_Whh0l; KT = 64;
    } else if (MODE == MODE_STEP1) {
        A0h = g_h0h[p ^ 1]; A0l = g_h0l[p ^ 1]; B0h = g_Wih1h; B0l = g_Wih1l;
        A1h = g_h1h[p];     A1l = g_h1l[p];     B1h = g_Whh1h; B1l = g_Whh1l; KT = 128;
    } else {
        A0h = g_outsh; A0l = g_outsl; B0h = g_fcwh; B0l = g_fcwl; KT = 64;
    }

    int m0, n0;
    if (MODE == MODE_LOGITS) { m0 = blockIdx.y * 64; n0 = blockIdx.x * 64; }
    else                     { m0 = blockIdx.x * 64; n0 = blockIdx.y * 64; }

    const int tid = threadIdx.x;
    const int lane = tid & 31;
    const int warp = tid >> 5;
    const int wm = warp & 1;    // 2 warps over M (32 rows each)
    const int wn = warp >> 1;   // 4 warps over N (16 cols each)

    // Smem byte bases
    const uint32_t smAh = (uint32_t)__cvta_generic_to_shared(&Ash[0][0][0]);
    const uint32_t smAl = (uint32_t)__cvta_generic_to_shared(&Asl[0][0][0]);
    const uint32_t smBh = (uint32_t)__cvta_generic_to_shared(&Bsh[0][0][0]);
    const uint32_t smBl = (uint32_t)__cvta_generic_to_shared(&Bsl[0][0][0]);

    // ldmatrix per-lane addresses:
    // A x4: m0:(rows0-7,k0-7) m1:(rows8-15,k0-7) m2:(rows0-7,k8-15) m3:(rows8-15,k8-15)
    const int rowA = (lane & 7) + ((lane >> 3) & 1) * 8;
    const int colA = (lane >> 4) * 8;
    // B x4: m0:(n0-7,k0-7) m1:(n0-7,k8-15) m2:(n8-15,k0-7) m3:(n8-15,k8-15)
    const int rowB = (lane & 7) + (lane >> 4) * 8;
    const int colB = ((lane >> 3) & 1) * 8;
    const uint32_t aOffH = smAh + (uint32_t)((wm * 32 + rowA) * ROWB + colA * 2);
    const uint32_t aOffL = smAl + (uint32_t)((wm * 32 + rowA) * ROWB + colA * 2);
    const uint32_t bOffH = smBh + (uint32_t)((wn * 16 + rowB) * ROWB + colB * 2);
    const uint32_t bOffL = smBl + (uint32_t)((wn * 16 + rowB) * ROWB + colB * 2);

    float accH[2][2][4];
    float accX[2][2][4];
#pragma unroll
    for (int i = 0; i < 2; i++)
#pragma unroll
        for (int j = 0; j < 2; j++)
#pragma unroll
            for (int k = 0; k < 4; k++) { accH[i][j][k] = 0.0f; accX[i][j][k] = 0.0f; }

    // cp.async tile load: each thread moves one 16B chunk per array per stage.
    const int lrow = tid >> 2;
    const int lc8 = (tid & 3) * 8;
    auto load_tile = [&](int kt, int s) {
        const __half *sAh = A0h, *sAl = A0l, *sBh = B0h, *sBl = B0l;
        int kk = kt * 32;
        if (MODE == MODE_STEP1 && kt >= 64) {
            sAh = A1h; sAl = A1l; sBh = B1h; sBl = B1l; kk = (kt - 64) * 32;
        }
        const size_t gA = (size_t)(m0 + lrow) * HH + kk + lc8;
        const size_t gB = (size_t)(n0 + lrow) * HH + kk + lc8;
        const uint32_t so = (uint32_t)(s * STAGEB + lrow * ROWB + lc8 * 2);
        cp16(smAh + so, sAh + gA);
        cp16(smAl + so, sAl + gA);
        cp16(smBh + so, sBh + gB);
        cp16(smBl + so, sBl + gB);
        asm volatile("cp.async.commit_group;\n" ::: "memory");
    };

    load_tile(0, 0);

    for (int kt = 0; kt < KT; kt++) {
        const int s = kt & 1;
        asm volatile("cp.async.wait_group 0;\n" ::: "memory");
        __syncthreads();
        if (kt + 1 < KT) load_tile(kt + 1, s ^ 1);

        const uint32_t sb = (uint32_t)(s * STAGEB);
#pragma unroll
        for (int ks = 0; ks < 2; ks++) {
            uint32_t ah[2][4], al[2][4], bh[4], bl[4];
            const uint32_t ko = (uint32_t)(ks * 32);  // 16 halves = 32B
#pragma unroll
            for (int mt = 0; mt < 2; mt++) {
                ldsm4(ah[mt], aOffH + sb + (uint32_t)(mt * 16 * ROWB) + ko);
                ldsm4(al[mt], aOffL + sb + (uint32_t)(mt * 16 * ROWB) + ko);
            }
            ldsm4(bh, bOffH + sb + ko);
            ldsm4(bl, bOffL + sb + ko);
#pragma unroll
            for (int mt = 0; mt < 2; mt++)
#pragma unroll
                for (int nt = 0; nt < 2; nt++) {
                    mma16(accH[mt][nt], ah[mt], bh + nt * 2);
                    mma16(accX[mt][nt], al[mt], bh + nt * 2);
                    mma16(accX[mt][nt], ah[mt], bl + nt * 2);
                }
        }
    }

    // Epilogue
#pragma unroll
    for (int mt = 0; mt < 2; mt++) {
#pragma unroll
        for (int hi = 0; hi < 2; hi++) {
            const int r = m0 + wm * 32 + mt * 16 + (lane >> 2) + hi * 8;
            int tokrow = 0;
            if (MODE == MODE_STEP0) tokrow = tokens[r * TT + t];
#pragma unroll
            for (int nt = 0; nt < 2; nt++) {
#pragma unroll
                for (int lo = 0; lo < 2; lo++) {
                    const int c = n0 + wn * 16 + nt * 8 + (lane & 3) * 2 + lo;
                    float v = accH[mt][nt][hi * 2 + lo] + accX[mt][nt][hi * 2 + lo] * LO_INV;
                    if (MODE == MODE_EPRIME) {
                        v += b_ih[c] + b_hh[c];
                        g_Eprime[(size_t)r * HH + c] = v;
                    } else if (MODE == MODE_STEP0) {
                        v += g_Eprime[(size_t)tokrow * HH + c];
                        v = my_tanh(v);
                        const size_t idx = (size_t)r * HH + c;
                        f16_split(v, g_h0h[p ^ 1][idx], g_h0l[p ^ 1][idx]);
                    } else if (MODE == MODE_STEP1) {
                        v += b_ih[HH + c] + b_hh[HH + c];
                        v = my_tanh(v);
                        const size_t idx = (size_t)r * HH + c;
                        __half vh, vl;
                        f16_split(v, vh, vl);
                        g_h1h[p ^ 1][idx] = vh;
                        g_h1l[p ^ 1][idx] = vl;
                        const size_t oidx = (size_t)t * BB * HH + idx;
                        g_outsh[oidx] = vh;
                        g_outsl[oidx] = vl;
                    } else {  // MODE_LOGITS
                        v += fc_b[c];
                        d_out[(size_t)r * VV + c] = v;
                    }
                }
            }
        }
    }
}

// ---------------------------------------------------------------------------
// h_final: reconstruct fp32 from hi/lo (last step wrote parity 0)
// ---------------------------------------------------------------------------
__global__ void final_copy_kernel(float* __restrict__ d_out) {
    int i = blockIdx.x * blockDim.x + threadIdx.x;
    if (i < BB * HH) {
        d_out[(size_t)TT * BB * VV + i] =
            __half2float(g_h0h[0][i]) + __half2float(g_h0l[0][i]) * LO_INV;
        d_out[(size_t)TT * BB * VV + BB * HH + i] =
            __half2float(g_h1h[0][i]) + __half2float(g_h1l[0][i]) * LO_INV;
    }
}

// ---------------------------------------------------------------------------
// Launch
// ---------------------------------------------------------------------------
extern "C" void kernel_launch(void* const* d_in, const int* in_sizes, int n_in,
                              void* d_out, int out_size) {
    const int*   tokens = (const int*)d_in[0];
    const float* h0     = (const float*)d_in[1];
    const float* emb    = (const float*)d_in[2];
    const float* Wih    = (const float*)d_in[3];
    const float* Whh    = (const float*)d_in[4];
    const float* bih    = (const float*)d_in[5];
    const float* bhh    = (const float*)d_in[6];
    const float* fcw    = (const float*)d_in[7];
    const float* fcb    = (const float*)d_in[8];
    float* out = (float*)d_out;

    // 1) Split weights + initial state into fp16 hi/lo
    prep_kernel<<<1024, 256>>>(h0, emb, Wih, Whh, fcw);

    // 2) E'' = emb @ W_ih0^T + b_ih0 + b_hh0
    gemm_kernel<MODE_EPRIME><<<dim3(VV / 64, HH / 64), 256>>>(
        tokens, bih, bhh, fcb, out, 0);

    // 3) Recurrence: 200 steps, 2 dependent GEMMs each
    for (int t = 0; t < TT; t++) {
        gemm_kernel<MODE_STEP0><<<dim3(BB / 64, HH / 64), 256>>>(
            tokens, bih, bhh, fcb, out, t);
        gemm_kernel<MODE_STEP1><<<dim3(BB / 64, HH / 64), 256>>>(
            tokens, bih, bhh, fcb, out, t);
    }

    // 4) Logits: [T*B, H] @ [V, H]^T + fc_b   (n-tile fastest for A reuse)
    gemm_kernel<MODE_LOGITS><<<dim3(VV / 64, (TT * BB) / 64), 256>>>(
        tokens, bih, bhh, fcb, out, 0);

    // 5) h_final
    if (out_size >= TT * BB * VV + LL * BB * HH)
        final_copy_kernel<<<(BB * HH + 255) / 256, 256>>>(out);
}